// round 1
// baseline (speedup 1.0000x reference)
#include <cuda_runtime.h>
#include <cuda_bf16.h>
#include <cstdint>

// ---------------------------------------------------------------------------
// DiffNet forward:
//   for (W,b) in [(W0,b0),(W1,b1)]:
//       agg = S @ U                      (COO spmm, row-normalized)
//       U   = relu(concat([agg, U]) @ W + b)
//   G = U + R @ V
//   out = [ G[batch_user], V[batch_pos], V[batch_neg] ]   (3 x [8192,64] f32)
//
// Inputs (metadata order):
//  0 batch_user(int32)[8192] 1 batch_pos(int32) 2 batch_neg(int32)
//  3 U f32[100000*64]  4 V f32[50000*64]
//  5 W0 f32[128*64] 6 b0 f32[64] 7 W1 f32[128*64] 8 b1 f32[64]
//  9 S_row i32[3.2M] 10 S_col 11 S_val f32
// 12 R_row i32[5M]  13 R_col 14 R_val f32
// ---------------------------------------------------------------------------

#define D 64
#define NUSERS_MAX 100000

// scratch (alloc-free rule: __device__ globals)
__device__ float g_agg[NUSERS_MAX * D];
__device__ float g_u1 [NUSERS_MAX * D];
__device__ float g_g  [NUSERS_MAX * D];

// ---------------------------------------------------------------------------
__global__ void zero_kernel(float* __restrict__ p, int n4) {
    int i = blockIdx.x * blockDim.x + threadIdx.x;
    if (i < n4) reinterpret_cast<float4*>(p)[i] = make_float4(0.f, 0.f, 0.f, 0.f);
}

// COO spmm scatter: Y[row[e]] += val[e] * X[col[e]],  16 threads per edge,
// each thread handles a float4 slice and issues one vector reduction.
__global__ void spmm_kernel(const int* __restrict__ row,
                            const int* __restrict__ col,
                            const float* __restrict__ val,
                            const float* __restrict__ X,
                            float* __restrict__ Y,
                            int nnz) {
    long long idx = (long long)blockIdx.x * blockDim.x + threadIdx.x;
    int e    = (int)(idx >> 4);
    int lane = (int)(idx & 15);
    if (e >= nnz) return;
    int   r = __ldg(row + e);
    int   c = __ldg(col + e);
    float v = __ldg(val + e);
    float4 x = *reinterpret_cast<const float4*>(X + (long long)c * D + lane * 4);
    float* dst = Y + (long long)r * D + lane * 4;
    asm volatile("red.global.add.v4.f32 [%0], {%1,%2,%3,%4};"
                 :: "l"(dst), "f"(v * x.x), "f"(v * x.y), "f"(v * x.z), "f"(v * x.w)
                 : "memory");
}

// out[r] = relu( concat(A[r], Uin[r]) @ W + b ), W: [128,64], per-row.
// Block: 256 threads = 8 warps; each warp handles 2 rows; lane -> (subrow, 4 cols).
// W + b staged in smem once per block; grid-stride over 16-row tiles.
__global__ __launch_bounds__(256)
void dense_kernel(const float* __restrict__ A,
                  const float* __restrict__ Uin,
                  const float* __restrict__ W,
                  const float* __restrict__ b,
                  float* __restrict__ out,
                  int nrows) {
    __shared__ float Ws[2 * D * D];     // 32 KB
    __shared__ float bs[D];
    __shared__ float xs[8][2][2 * D];   // 8 warps x 2 rows x 128 floats

    int tid = threadIdx.x;
    for (int i = tid; i < 2 * D * D; i += 256) Ws[i] = W[i];
    if (tid < D) bs[tid] = b[tid];
    __syncthreads();

    int warp = tid >> 5, lane = tid & 31;
    int subrow = lane >> 4;        // 0 or 1
    int cg     = lane & 15;        // column group (4 cols)

    for (int base = blockIdx.x * 16; base < nrows; base += gridDim.x * 16) {
        int r = base + warp * 2 + subrow;
        // stage concat row: lanes 0-15 load A-half, 16-31 load Uin-half (per subrow? no:
        // each warp loads both of its rows cooperatively)
        {
            // lane l: rows rr = l>>4 handled above; simpler: each lane loads one float4
            // layout: 2 rows * 128 floats = 64 float4 slots; 32 lanes * 2 iters
            #pragma unroll
            for (int it = 0; it < 2; it++) {
                int slot = it * 32 + lane;     // 0..63
                int rr   = slot >> 5;          // row 0/1
                int off  = (slot & 31) * 4;    // 0..124
                int rowg = base + warp * 2 + rr;
                float4 vv;
                if (off < D) vv = *reinterpret_cast<const float4*>(A   + (long long)rowg * D + off);
                else         vv = *reinterpret_cast<const float4*>(Uin + (long long)rowg * D + (off - D));
                *reinterpret_cast<float4*>(&xs[warp][rr][off]) = vv;
            }
        }
        __syncwarp();

        float4 acc = *reinterpret_cast<const float4*>(&bs[cg * 4]);
        const float* xr = xs[warp][subrow];
        #pragma unroll 8
        for (int k = 0; k < 2 * D; k++) {
            float xk = xr[k];
            float4 w = *reinterpret_cast<const float4*>(&Ws[k * D + cg * 4]);
            acc.x = fmaf(xk, w.x, acc.x);
            acc.y = fmaf(xk, w.y, acc.y);
            acc.z = fmaf(xk, w.z, acc.z);
            acc.w = fmaf(xk, w.w, acc.w);
        }
        acc.x = fmaxf(acc.x, 0.f); acc.y = fmaxf(acc.y, 0.f);
        acc.z = fmaxf(acc.z, 0.f); acc.w = fmaxf(acc.w, 0.f);
        *reinterpret_cast<float4*>(out + (long long)r * D + cg * 4) = acc;
        __syncwarp();
    }
}

// out = [G[bu]; V[bp]; V[bn]]  each [B, 64] f32. One thread per float4.
__global__ void gather_kernel(const int* __restrict__ bu,
                              const int* __restrict__ bp,
                              const int* __restrict__ bn,
                              const float* __restrict__ G,
                              const float* __restrict__ V,
                              float* __restrict__ out,
                              int B) {
    int i = blockIdx.x * blockDim.x + threadIdx.x;   // B*16 per section
    int total = 3 * B * 16;
    if (i >= total) return;
    int sec  = i / (B * 16);
    int rem  = i - sec * (B * 16);
    int r    = rem >> 4;
    int lane = rem & 15;
    const float* src;
    if (sec == 0)      src = G + (long long)__ldg(bu + r) * D;
    else if (sec == 1) src = V + (long long)__ldg(bp + r) * D;
    else               src = V + (long long)__ldg(bn + r) * D;
    reinterpret_cast<float4*>(out)[i] =
        *reinterpret_cast<const float4*>(src + lane * 4);
}

// ---------------------------------------------------------------------------
extern "C" void kernel_launch(void* const* d_in, const int* in_sizes, int n_in,
                              void* d_out, int out_size) {
    const int*   bu    = (const int*)  d_in[0];
    const int*   bp    = (const int*)  d_in[1];
    const int*   bn    = (const int*)  d_in[2];
    const float* U     = (const float*)d_in[3];
    const float* V     = (const float*)d_in[4];
    const float* W0    = (const float*)d_in[5];
    const float* b0    = (const float*)d_in[6];
    const float* W1    = (const float*)d_in[7];
    const float* b1    = (const float*)d_in[8];
    const int*   S_row = (const int*)  d_in[9];
    const int*   S_col = (const int*)  d_in[10];
    const float* S_val = (const float*)d_in[11];
    const int*   R_row = (const int*)  d_in[12];
    const int*   R_col = (const int*)  d_in[13];
    const float* R_val = (const float*)d_in[14];

    int B       = in_sizes[0];
    int n_users = in_sizes[3] / D;
    int s_nnz   = in_sizes[9];
    int r_nnz   = in_sizes[12];

    float *agg, *u1, *gg;
    cudaGetSymbolAddress((void**)&agg, g_agg);
    cudaGetSymbolAddress((void**)&u1,  g_u1);
    cudaGetSymbolAddress((void**)&gg,  g_g);

    int n4 = n_users * D / 4;
    int zb = (n4 + 255) / 256;

    long long s_threads = (long long)s_nnz * 16;
    int s_blocks = (int)((s_threads + 255) / 256);
    long long r_threads = (long long)r_nnz * 16;
    int r_blocks = (int)((r_threads + 255) / 256);

    const int DENSE_BLOCKS = 592;   // ~4/SM; grid-stride amortizes W smem stage

    // Layer 0
    zero_kernel<<<zb, 256>>>(agg, n4);
    spmm_kernel<<<s_blocks, 256>>>(S_row, S_col, S_val, U, agg, s_nnz);
    dense_kernel<<<DENSE_BLOCKS, 256>>>(agg, U, W0, b0, u1, n_users);
    // Layer 1 (write result straight into G)
    zero_kernel<<<zb, 256>>>(agg, n4);
    spmm_kernel<<<s_blocks, 256>>>(S_row, S_col, S_val, u1, agg, s_nnz);
    dense_kernel<<<DENSE_BLOCKS, 256>>>(agg, u1, W1, b1, gg, n_users);
    // G += R @ V
    spmm_kernel<<<r_blocks, 256>>>(R_row, R_col, R_val, V, gg, r_nnz);
    // Gather outputs
    int g_total  = 3 * B * 16;
    int g_blocks = (g_total + 255) / 256;
    gather_kernel<<<g_blocks, 256>>>(bu, bp, bn, gg, V, (float*)d_out, B);
}